// round 7
// baseline (speedup 1.0000x reference)
#include <cuda_runtime.h>
#include <cuda_bf16.h>
#include <cstdint>

#define BATCH 64
#define D 256
#define NTOK 4095
#define NCH 40            // 24 (layer1 K=768) + 8 (layer2) + 8 (layer3), K-chunk = 32
#define WCHUNK 32768      // bytes per W chunk (frag-major, hi+lo packed)

__device__ float g_node_val[2047 * BATCH * D];
__device__ __align__(256) uint4 g_W[NCH * 2048];   // 1.25 MB

// ---------------- helpers ----------------
__device__ __forceinline__ uint32_t smem_u32(const void* p) {
    uint32_t a;
    asm("{ .reg .u64 t; cvta.to.shared.u64 t, %1; cvt.u32.u64 %0, t; }" : "=r"(a) : "l"(p));
    return a;
}
__device__ __forceinline__ void cp_async16(uint32_t dst, const void* src) {
    asm volatile("cp.async.cg.shared.global [%0], [%1], 16;" :: "r"(dst), "l"(src) : "memory");
}
__device__ __forceinline__ void cp_commit() { asm volatile("cp.async.commit_group;" ::: "memory"); }
template<int N> __device__ __forceinline__ void cp_wait() {
    asm volatile("cp.async.wait_group %0;" :: "n"(N) : "memory");
}
__device__ __forceinline__ void mma16816(float d[4], uint32_t a0, uint32_t a1, uint32_t a2, uint32_t a3,
                                         uint32_t b0, uint32_t b1) {
    asm volatile("mma.sync.aligned.m16n8k16.row.col.f32.bf16.bf16.f32 "
                 "{%0,%1,%2,%3}, {%4,%5,%6,%7}, {%8,%9}, {%0,%1,%2,%3};"
                 : "+f"(d[0]), "+f"(d[1]), "+f"(d[2]), "+f"(d[3])
                 : "r"(a0), "r"(a1), "r"(a2), "r"(a3), "r"(b0), "r"(b1));
}
__device__ __forceinline__ uint32_t b2u(__nv_bfloat162 v) { return *reinterpret_cast<uint32_t*>(&v); }
__device__ __forceinline__ void split2(float x, float y, uint32_t& h, uint32_t& l) {
    __nv_bfloat162 hh = __floats2bfloat162_rn(x, y);
    __nv_bfloat162 ll = __floats2bfloat162_rn(x - __bfloat162float(hh.x),
                                              y - __bfloat162float(hh.y));
    h = b2u(hh); l = b2u(ll);
}

// -------- weight prep: fp32 -> hi/lo bf16, frag-major (one LDS.128 = hi+lo B frags) --------
// g_W[((gc*2+s)*32 + jt)*32 + lane] = {b0h, b1h, b0l, b1l}
__global__ void prep_weights(const float* __restrict__ W_in,
                             const float* __restrict__ W1,
                             const float* __restrict__ W2) {
    int idx = blockIdx.x * 256 + threadIdx.x;
    if (idx >= NCH * 2048) return;
    int lane = idx & 31;
    int jt   = (idx >> 5) & 31;
    int s    = (idx >> 10) & 1;
    int gcw  = idx >> 11;
    int n  = jt * 8 + (lane >> 2);
    int tg = lane & 3;
    const float* Wsrc; int K, kb;
    if (gcw < 24)      { Wsrc = W_in; K = 768; kb = gcw * 32; }
    else if (gcw < 32) { Wsrc = W1;   K = 256; kb = (gcw - 24) * 32; }
    else               { Wsrc = W2;   K = 256; kb = (gcw - 32) * 32; }
    int k0 = kb + s * 16 + tg * 2;
    uint32_t h0, l0, h1, l1;
    split2(Wsrc[n * K + k0],     Wsrc[n * K + k0 + 1], h0, l0);
    split2(Wsrc[n * K + k0 + 8], Wsrc[n * K + k0 + 9], h1, l1);
    g_W[idx] = make_uint4(h0, h1, l0, l1);
}

// ---------------- fused 3-layer MLP kernel, 512 threads, templated on block M ----------------
template<int MROWS>
__global__ void __launch_bounds__(512, 1)
level_kernel(const int* __restrict__ tokens, const float* __restrict__ E,
             const float* __restrict__ b_in, const float* __restrict__ b1,
             const float* __restrict__ b2, float* __restrict__ d_out, int level)
{
    constexpr int NT    = MROWS / 16;    // m16 tiles in block
    constexpr int IT    = MROWS / 32;    // m16 tiles per warp
    constexpr int ASLOT = NT * 2048;     // layer-1 A slot bytes (hi+lo)
    constexpr int ALO1  = NT * 1024;     // lo offset within As slot
    constexpr int AFLO  = NT * 8192;     // lo offset within Af
    constexpr int BIGOFF  = 65536;
    constexpr int BIASOFF = BIGOFF + 2 * NT * 8192;
    constexpr int RPTROFF = BIASOFF + 3072;

    extern __shared__ char smem[];
    float* bias = (float*)(smem + BIASOFF);
    const float** rowptr = (const float**)(smem + RPTROFF);
    char* As = smem + BIGOFF;
    char* Af = smem + BIGOFF;
    const uint32_t sbW = smem_u32(smem);

    const int tid  = threadIdx.x;
    const int wid  = tid >> 5;
    const int lane = tid & 31;
    const int g    = lane >> 2;
    const int tig  = lane & 3;
    const int wm   = wid & 1;       // M half
    const int wn   = wid >> 1;      // N eighth (32 cols)
    const int nA   = level - 1 + (MROWS / 64) * blockIdx.x;

    if (tid < 256) {
        bias[tid]       = b_in[tid];
        bias[256 + tid] = b1[tid];
        bias[512 + tid] = b2[tid];
    }
    if (tid < MROWS) {
        int row = tid;
        int node = nA + (row >> 6);
        int b = row & 63;
        rowptr[row] = E + (size_t)tokens[b * NTOK + node] * D;
        if (level == 1024) {
            rowptr[MROWS + row]     = E + (size_t)tokens[b * NTOK + 2 * node + 1] * D;
            rowptr[2 * MROWS + row] = E + (size_t)tokens[b * NTOK + 2 * node + 2] * D;
        } else {
            rowptr[MROWS + row]     = g_node_val + ((size_t)(2 * node + 1) * BATCH + b) * D;
            rowptr[2 * MROWS + row] = g_node_val + ((size_t)(2 * node + 2) * BATCH + b) * D;
        }
    }

    float acc[IT][4][4];
    #pragma unroll
    for (int i = 0; i < IT; ++i)
        #pragma unroll
        for (int j = 0; j < 4; ++j)
            #pragma unroll
            for (int q = 0; q < 4; ++q) acc[i][j][q] = 0.f;

    // gather index precompute
    int grow, gq;
    if (MROWS == 128) { grow = tid >> 2; gq = tid & 3; }
    else              { grow = tid >> 3; gq = tid & 7; }
    const int gt   = grow >> 4;
    const int gg   = grow & 7;
    const int grhi = (grow >> 3) & 1;

    // ---- prologue: W(0) async copy ----
    {
        const char* src = (const char*)g_W;
        #pragma unroll
        for (int r = 0; r < 4; ++r)
            cp_async16(sbW + tid * 16 + r * 8192, src + tid * 16 + r * 8192);
        cp_commit();
    }
    __syncthreads();   // rowptr visible
    // ---- A(0) gather ----
    {
        if (MROWS == 128) {
            const float* src = rowptr[grow] + gq * 8;
            float4 p0 = ((const float4*)src)[0], p1 = ((const float4*)src)[1];
            int s = gq >> 1, khalf = gq & 1;
            char* base = As + (gt * 2 + s) * 512 + grhi * 4 + khalf * 8;
            const float* pf = (const float*)&p0;
            #pragma unroll
            for (int m = 0; m < 4; ++m) {
                uint32_t h, l;
                split2(pf[2 * m], pf[2 * m + 1], h, l);
                char* a = base + (gg * 4 + m) * 16;
                *(uint32_t*)a = h;
                *(uint32_t*)(a + ALO1) = l;
            }
        } else {
            const float* src = rowptr[grow] + gq * 4;
            float4 p0 = ((const float4*)src)[0];
            int s = gq >> 2, khalf = (gq >> 1) & 1;
            char* base = As + (gt * 2 + s) * 512 + grhi * 4 + khalf * 8;
            const float* pf = (const float*)&p0;
            #pragma unroll
            for (int u = 0; u < 2; ++u) {
                uint32_t h, l;
                split2(pf[2 * u], pf[2 * u + 1], h, l);
                char* a = base + (gg * 4 + (gq & 1) * 2 + u) * 16;
                *(uint32_t*)a = h;
                *(uint32_t*)(a + ALO1) = l;
            }
        }
    }
    cp_wait<0>();
    __syncthreads();

    // ---- main chunk loop ----
    for (int gc = 0; gc < NCH; ++gc) {
        const int slot = gc & 1;
        const bool doGather = (gc + 1 < 24);

        // prefetch next A rows into registers
        float4 p0, p1;
        if (doGather) {
            int gn = gc + 1;
            if (MROWS == 128) {
                const float* src = rowptr[(gn >> 3) * 128 + grow] + (gn & 7) * 32 + gq * 8;
                p0 = ((const float4*)src)[0]; p1 = ((const float4*)src)[1];
            } else {
                const float* src = rowptr[(gn >> 3) * 64 + grow] + (gn & 7) * 32 + gq * 4;
                p0 = ((const float4*)src)[0];
            }
        }
        // prefetch next W chunk
        if (gc + 1 < NCH) {
            const char* src = (const char*)g_W + (size_t)(gc + 1) * WCHUNK;
            uint32_t dst = sbW + ((gc + 1) & 1) * WCHUNK;
            #pragma unroll
            for (int r = 0; r < 4; ++r)
                cp_async16(dst + tid * 16 + r * 8192, src + tid * 16 + r * 8192);
            cp_commit();
        }

        // ---- compute chunk ----
        const char* Wslot = smem + slot * WCHUNK;
        const int layer = (gc < 24) ? 0 : (gc < 32) ? 1 : 2;
        const int c = (layer == 0) ? 0 : (layer == 1) ? (gc - 24) : (gc - 32);
        #pragma unroll
        for (int ks = 0; ks < 2; ++ks) {
            uint4 Ahi[IT], Alo[IT];
            if (layer == 0) {
                const char* ab = As + slot * ASLOT;
                #pragma unroll
                for (int i = 0; i < IT; ++i) {
                    const char* p = ab + (((wm * IT + i) * 2 + ks) * 32 + lane) * 16;
                    Ahi[i] = *(const uint4*)p;
                    Alo[i] = *(const uint4*)(p + ALO1);
                }
            } else {
                int sg = c * 2 + ks;
                #pragma unroll
                for (int i = 0; i < IT; ++i) {
                    const char* p = Af + (((wm * IT + i) * 16 + sg) * 32 + lane) * 16;
                    Ahi[i] = *(const uint4*)p;
                    Alo[i] = *(const uint4*)(p + AFLO);
                }
            }
            #pragma unroll
            for (int j = 0; j < 4; ++j) {
                uint4 B = *(const uint4*)(Wslot + ((ks * 32 + wn * 4 + j) * 32 + lane) * 16);
                #pragma unroll
                for (int i = 0; i < IT; ++i) {
                    mma16816(acc[i][j], Ahi[i].x, Ahi[i].y, Ahi[i].z, Ahi[i].w, B.x, B.y);
                    mma16816(acc[i][j], Ahi[i].x, Ahi[i].y, Ahi[i].z, Ahi[i].w, B.z, B.w);
                    mma16816(acc[i][j], Alo[i].x, Alo[i].y, Alo[i].z, Alo[i].w, B.x, B.y);
                }
            }
        }

        // store prefetched A rows into the other slot
        if (doGather) {
            char* sbase = As + (slot ^ 1) * ASLOT;
            if (MROWS == 128) {
                int s = gq >> 1, khalf = gq & 1;
                char* base = sbase + (gt * 2 + s) * 512 + grhi * 4 + khalf * 8;
                const float* pf0 = (const float*)&p0;
                const float* pf1 = (const float*)&p1;
                #pragma unroll
                for (int m = 0; m < 4; ++m) {
                    float x = (m < 2) ? pf0[2 * m] : pf1[2 * (m - 2)];
                    float y = (m < 2) ? pf0[2 * m + 1] : pf1[2 * (m - 2) + 1];
                    uint32_t h, l;
                    split2(x, y, h, l);
                    char* a = base + (gg * 4 + m) * 16;
                    *(uint32_t*)a = h;
                    *(uint32_t*)(a + ALO1) = l;
                }
            } else {
                int s = gq >> 2, khalf = (gq >> 1) & 1;
                char* base = sbase + (gt * 2 + s) * 512 + grhi * 4 + khalf * 8;
                const float* pf = (const float*)&p0;
                #pragma unroll
                for (int u = 0; u < 2; ++u) {
                    uint32_t h, l;
                    split2(pf[2 * u], pf[2 * u + 1], h, l);
                    char* a = base + (gg * 4 + (gq & 1) * 2 + u) * 16;
                    *(uint32_t*)a = h;
                    *(uint32_t*)(a + ALO1) = l;
                }
            }
        }
        cp_wait<0>();
        __syncthreads();

        // ---- mid epilogue after layers 1 and 2: bias+ELU+split -> Af (frag-major) ----
        if (gc == 23 || gc == 31) {
            const float* bp = bias + ((gc == 23) ? 0 : 256);
            #pragma unroll
            for (int i = 0; i < IT; ++i) {
                int t_m = wm * IT + i;
                #pragma unroll
                for (int j = 0; j < 4; ++j) {
                    int cb = wn * 32 + j * 8 + tig * 2;
                    float b0v = bp[cb], b1v = bp[cb + 1];
                    float v0 = acc[i][j][0] + b0v, v1 = acc[i][j][1] + b1v;
                    float v2 = acc[i][j][2] + b0v, v3 = acc[i][j][3] + b1v;
                    v0 = v0 > 0.f ? v0 : (__expf(v0) - 1.f);
                    v1 = v1 > 0.f ? v1 : (__expf(v1) - 1.f);
                    v2 = v2 > 0.f ? v2 : (__expf(v2) - 1.f);
                    v3 = v3 > 0.f ? v3 : (__expf(v3) - 1.f);
                    uint32_t h01, l01, h23, l23;
                    split2(v0, v1, h01, l01);
                    split2(v2, v3, h23, l23);
                    int sg = wn * 2 + (j >> 1);
                    int khalf = j & 1;
                    char* a = Af + ((t_m * 16 + sg) * 32 + lane) * 16 + khalf * 8;
                    *(uint2*)a = make_uint2(h01, h23);
                    *(uint2*)(a + AFLO) = make_uint2(l01, l23);
                    acc[i][j][0] = acc[i][j][1] = acc[i][j][2] = acc[i][j][3] = 0.f;
                }
            }
            __syncthreads();
        }
    }

    // ---- final epilogue: fragments + b2 + residual, direct coalesced-by-quad stores ----
    #pragma unroll
    for (int i = 0; i < IT; ++i) {
        int r_g  = wm * (MROWS / 2) + i * 16 + g;
        int r_g8 = r_g + 8;
        const float* e0p = rowptr[r_g];
        const float* e1p = rowptr[r_g8];
        #pragma unroll
        for (int j = 0; j < 4; ++j) {
            int cb = wn * 32 + j * 8 + tig * 2;
            float b0v = bias[512 + cb], b1v = bias[512 + cb + 1];
            float2 e0 = *(const float2*)(e0p + cb);
            float2 e1 = *(const float2*)(e1p + cb);
            float2 o0 = make_float2(acc[i][j][0] + b0v + e0.x, acc[i][j][1] + b1v + e0.y);
            float2 o1 = make_float2(acc[i][j][2] + b0v + e1.x, acc[i][j][3] + b1v + e1.y);
            if (level == 1) {
                *(float2*)(d_out + (size_t)r_g  * D + cb) = o0;
                *(float2*)(d_out + (size_t)r_g8 * D + cb) = o1;
            } else {
                int n0 = nA + (r_g >> 6), n1 = nA + (r_g8 >> 6);
                *(float2*)(g_node_val + ((size_t)n0 * BATCH + (r_g  & 63)) * D + cb) = o0;
                *(float2*)(g_node_val + ((size_t)n1 * BATCH + (r_g8 & 63)) * D + cb) = o1;
            }
        }
    }
}

extern "C" void kernel_launch(void* const* d_in, const int* in_sizes, int n_in,
                              void* d_out, int out_size) {
    const int*   tokens = (const int*)d_in[0];
    const float* E      = (const float*)d_in[1];
    const float* W_in   = (const float*)d_in[2];
    const float* b_in   = (const float*)d_in[3];
    const float* W1     = (const float*)d_in[4];
    const float* b1     = (const float*)d_in[5];
    const float* W2     = (const float*)d_in[6];
    const float* b2     = (const float*)d_in[7];
    float* out = (float*)d_out;

    const int SM128 = 65536 + 2 * 8 * 8192 + 3072 + 3 * 128 * 8;  // 202752
    const int SM64  = 65536 + 2 * 4 * 8192 + 3072 + 3 * 64 * 8;   // 135680
    cudaFuncSetAttribute(level_kernel<128>, cudaFuncAttributeMaxDynamicSharedMemorySize, SM128);
    cudaFuncSetAttribute(level_kernel<64>,  cudaFuncAttributeMaxDynamicSharedMemorySize, SM64);

    prep_weights<<<(NCH * 2048 + 255) / 256, 256>>>(W_in, W1, W2);

    for (int level = 1024; level >= 1; level >>= 1) {
        if (level >= 512) {
            level_kernel<128><<<level / 2, 512, SM128>>>(tokens, E, b_in, b1, b2, out, level);
        } else {
            level_kernel<64><<<level, 512, SM64>>>(tokens, E, b_in, b1, b2, out, level);
        }
    }
}

// round 8
// speedup vs baseline: 1.1457x; 1.1457x over previous
#include <cuda_runtime.h>
#include <cuda_bf16.h>
#include <cstdint>

#define BATCH 64
#define D 256
#define NTOK 4095
#define NCH 20             // 12 (layer1 K=768) + 4 (layer2) + 4 (layer3), K-chunk = 64
#define WSLOT 65536        // bytes per W chunk (frag-major, hi+lo packed in uint4)

__device__ float g_node_val[2047 * BATCH * D];
__device__ __align__(256) uint4 g_W[NCH * 4096];   // 1.25 MB

// ---------------- SMEM layout ----------------
#define ASLOT   16896      // per layer-1 A slot: hi 16*528 + lo 16*528
#define ALO     8448
#define AFLO    32768      // Af lo offset (hi = 4 tiles * 16 sg * 32 lanes * 16B)
#define BIGOFF  131072     // after 2 W slots
#define BIASOFF 196608     // BIGOFF + 65536 (Af size; A ring aliases low part)
#define RPTROFF 199680
#define SMEM_TOTAL 201216

// ---------------- helpers ----------------
__device__ __forceinline__ uint32_t smem_u32(const void* p) {
    uint32_t a;
    asm("{ .reg .u64 t; cvta.to.shared.u64 t, %1; cvt.u32.u64 %0, t; }" : "=r"(a) : "l"(p));
    return a;
}
__device__ __forceinline__ void cp_async16(uint32_t dst, const void* src) {
    asm volatile("cp.async.cg.shared.global [%0], [%1], 16;" :: "r"(dst), "l"(src) : "memory");
}
__device__ __forceinline__ void cp_commit() { asm volatile("cp.async.commit_group;" ::: "memory"); }
template<int N> __device__ __forceinline__ void cp_wait() {
    asm volatile("cp.async.wait_group %0;" :: "n"(N) : "memory");
}
__device__ __forceinline__ void mma16816(float d[4], uint32_t a0, uint32_t a1, uint32_t a2, uint32_t a3,
                                         uint32_t b0, uint32_t b1) {
    asm volatile("mma.sync.aligned.m16n8k16.row.col.f32.bf16.bf16.f32 "
                 "{%0,%1,%2,%3}, {%4,%5,%6,%7}, {%8,%9}, {%0,%1,%2,%3};"
                 : "+f"(d[0]), "+f"(d[1]), "+f"(d[2]), "+f"(d[3])
                 : "r"(a0), "r"(a1), "r"(a2), "r"(a3), "r"(b0), "r"(b1));
}
__device__ __forceinline__ uint32_t b2u(__nv_bfloat162 v) { return *reinterpret_cast<uint32_t*>(&v); }
__device__ __forceinline__ uint32_t splith(float x, float y, uint32_t& l) {
    __nv_bfloat162 hh = __floats2bfloat162_rn(x, y);
    __nv_bfloat162 ll = __floats2bfloat162_rn(x - __bfloat162float(hh.x),
                                              y - __bfloat162float(hh.y));
    l = b2u(ll);
    return b2u(hh);
}

// -------- weight prep: fp32 -> hi/lo bf16, frag-major K64 chunks --------
// g_W[((gc*4+s)*32 + jt)*32 + lane] = {b0h, b1h, b0l, b1l}
__global__ void prep_weights(const float* __restrict__ W_in,
                             const float* __restrict__ W1,
                             const float* __restrict__ W2) {
    int idx = blockIdx.x * 256 + threadIdx.x;
    if (idx >= NCH * 4096) return;
    int lane = idx & 31;
    int jt   = (idx >> 5) & 31;
    int s    = (idx >> 10) & 3;
    int gcw  = idx >> 12;
    int n  = jt * 8 + (lane >> 2);
    int tg = lane & 3;
    const float* Wsrc; int K, kb;
    if (gcw < 12)      { Wsrc = W_in; K = 768; kb = gcw * 64; }
    else if (gcw < 16) { Wsrc = W1;   K = 256; kb = (gcw - 12) * 64; }
    else               { Wsrc = W2;   K = 256; kb = (gcw - 16) * 64; }
    int k0 = kb + s * 16 + tg * 2;
    uint32_t l0, l1;
    uint32_t h0 = splith(Wsrc[n * K + k0],     Wsrc[n * K + k0 + 1], l0);
    uint32_t h1 = splith(Wsrc[n * K + k0 + 8], Wsrc[n * K + k0 + 9], l1);
    g_W[idx] = make_uint4(h0, h1, l0, l1);
}

// ---------------- fused 3-layer MLP, M=64 node-block, 256 threads ----------------
__global__ void __launch_bounds__(256, 1)
level_kernel(const int* __restrict__ tokens, const float* __restrict__ E,
             const float* __restrict__ b_in, const float* __restrict__ b1,
             const float* __restrict__ b2, float* __restrict__ d_out, int level)
{
    extern __shared__ char smem[];
    float* bias = (float*)(smem + BIASOFF);
    const float** rowptr = (const float**)(smem + RPTROFF);
    char* As = smem + BIGOFF;
    char* Af = smem + BIGOFF;
    const uint32_t sbW = smem_u32(smem);

    const int tid  = threadIdx.x;
    const int wn   = tid >> 5;        // warp: 32 output cols each
    const int lane = tid & 31;
    const int g    = lane >> 2;
    const int tig  = lane & 3;
    const int node = level - 1 + blockIdx.x;

    // gather decode: combo c = t*4+s (t = m16 tile, s = kstep), 16 threads per combo
    const int gc_  = tid >> 4;
    const int gt   = gc_ >> 2;
    const int gs   = gc_ & 3;
    const int grg  = (tid >> 2) & 3;
    const int gtig = tid & 3;
    const int gr0  = gt * 16 + grg;

    bias[tid]       = b_in[tid];
    bias[256 + tid] = b1[tid];
    bias[512 + tid] = b2[tid];
    if (tid < 64) {
        int b = tid;
        rowptr[tid] = E + (size_t)tokens[b * NTOK + node] * D;
        if (level == 1024) {
            rowptr[64 + tid]  = E + (size_t)tokens[b * NTOK + 2 * node + 1] * D;
            rowptr[128 + tid] = E + (size_t)tokens[b * NTOK + 2 * node + 2] * D;
        } else {
            rowptr[64 + tid]  = g_node_val + ((size_t)(2 * node + 1) * BATCH + b) * D;
            rowptr[128 + tid] = g_node_val + ((size_t)(2 * node + 2) * BATCH + b) * D;
        }
    }

    float acc[4][4][4];
    #pragma unroll
    for (int i = 0; i < 4; ++i)
        #pragma unroll
        for (int j = 0; j < 4; ++j)
            #pragma unroll
            for (int q = 0; q < 4; ++q) acc[i][j][q] = 0.f;

    // ---- prologue: W(0) copy ----
    {
        const char* src = (const char*)g_W;
        #pragma unroll
        for (int r = 0; r < 16; ++r)
            cp_async16(sbW + tid * 16 + r * 4096, src + tid * 16 + r * 4096);
        cp_commit();
    }
    __syncthreads();   // rowptr visible
    // ---- A(0) gather: conflict-tuned STS.128 fragment lines ----
    {
        const float* pr0 = rowptr[gr0];
        const float* pr1 = rowptr[gr0 + 8];
        const float* pr2 = rowptr[gr0 + 4];
        const float* pr3 = rowptr[gr0 + 12];
        int kb = gs * 16 + gtig * 2;
        float2 a0 = *(const float2*)(pr0 + kb),     a1 = *(const float2*)(pr1 + kb);
        float2 a2 = *(const float2*)(pr0 + kb + 8), a3 = *(const float2*)(pr1 + kb + 8);
        float2 c0 = *(const float2*)(pr2 + kb),     c1 = *(const float2*)(pr3 + kb);
        float2 c2 = *(const float2*)(pr2 + kb + 8), c3 = *(const float2*)(pr3 + kb + 8);
        uint4 h1v, l1v, h2v, l2v;
        h1v.x = splith(a0.x, a0.y, l1v.x); h1v.y = splith(a1.x, a1.y, l1v.y);
        h1v.z = splith(a2.x, a2.y, l1v.z); h1v.w = splith(a3.x, a3.y, l1v.w);
        h2v.x = splith(c0.x, c0.y, l2v.x); h2v.y = splith(c1.x, c1.y, l2v.y);
        h2v.z = splith(c2.x, c2.y, l2v.z); h2v.w = splith(c3.x, c3.y, l2v.w);
        char* b1p = As + gc_ * 528 + (grg * 4 + gtig) * 16;
        char* b2p = As + gc_ * 528 + ((grg + 4) * 4 + gtig) * 16;
        *(uint4*)b1p = h1v; *(uint4*)(b1p + ALO) = l1v;
        *(uint4*)b2p = h2v; *(uint4*)(b2p + ALO) = l2v;
    }
    cp_wait<0>();
    __syncthreads();

    // ---- main chunk loop ----
    for (int gcc = 0; gcc < NCH; ++gcc) {
        const int slot = gcc & 1;
        const bool doGather = (gcc + 1 < 12);

        // prefetch next-chunk A rows (registers)
        float2 a0, a1, a2, a3, c0, c1, c2, c3;
        if (doGather) {
            int gn = gcc + 1;
            int seg = gn >> 2;
            int kb = (gn & 3) * 64 + gs * 16 + gtig * 2;
            const float* pr0 = rowptr[seg * 64 + gr0];
            const float* pr1 = rowptr[seg * 64 + gr0 + 8];
            const float* pr2 = rowptr[seg * 64 + gr0 + 4];
            const float* pr3 = rowptr[seg * 64 + gr0 + 12];
            a0 = *(const float2*)(pr0 + kb);     a1 = *(const float2*)(pr1 + kb);
            a2 = *(const float2*)(pr0 + kb + 8); a3 = *(const float2*)(pr1 + kb + 8);
            c0 = *(const float2*)(pr2 + kb);     c1 = *(const float2*)(pr3 + kb);
            c2 = *(const float2*)(pr2 + kb + 8); c3 = *(const float2*)(pr3 + kb + 8);
        }
        // prefetch next W chunk
        if (gcc + 1 < NCH) {
            const char* src = (const char*)g_W + (size_t)(gcc + 1) * WSLOT;
            uint32_t dst = sbW + ((gcc + 1) & 1) * WSLOT;
            #pragma unroll
            for (int r = 0; r < 16; ++r)
                cp_async16(dst + tid * 16 + r * 4096, src + tid * 16 + r * 4096);
            cp_commit();
        }

        // ---- compute chunk: K = 64 (4 ksteps) ----
        const char* Wslot = smem + slot * WSLOT;
        const int layer = (gcc < 12) ? 0 : (gcc < 16) ? 1 : 2;
        const int cIn = (layer == 1) ? (gcc - 12) : (gcc - 16);
        #pragma unroll
        for (int ks = 0; ks < 4; ++ks) {
            uint4 Ahi[4], Alo[4];
            if (layer == 0) {
                const char* ab = As + slot * ASLOT;
                #pragma unroll
                for (int i = 0; i < 4; ++i) {
                    const char* p = ab + (i * 4 + ks) * 528 + lane * 16;
                    Ahi[i] = *(const uint4*)p;
                    Alo[i] = *(const uint4*)(p + ALO);
                }
            } else {
                int sg = cIn * 4 + ks;
                #pragma unroll
                for (int i = 0; i < 4; ++i) {
                    const char* p = Af + ((i * 16 + sg) * 32 + lane) * 16;
                    Ahi[i] = *(const uint4*)p;
                    Alo[i] = *(const uint4*)(p + AFLO);
                }
            }
            #pragma unroll
            for (int j = 0; j < 4; ++j) {
                uint4 B = *(const uint4*)(Wslot + ((ks * 32 + wn * 4 + j) * 32 + lane) * 16);
                #pragma unroll
                for (int i = 0; i < 4; ++i) {
                    mma16816(acc[i][j], Ahi[i].x, Ahi[i].y, Ahi[i].z, Ahi[i].w, B.x, B.y);
                    mma16816(acc[i][j], Ahi[i].x, Ahi[i].y, Ahi[i].z, Ahi[i].w, B.z, B.w);
                    mma16816(acc[i][j], Alo[i].x, Alo[i].y, Alo[i].z, Alo[i].w, B.x, B.y);
                }
            }
        }

        // store prefetched A into other slot
        if (doGather) {
            uint4 h1v, l1v, h2v, l2v;
            h1v.x = splith(a0.x, a0.y, l1v.x); h1v.y = splith(a1.x, a1.y, l1v.y);
            h1v.z = splith(a2.x, a2.y, l1v.z); h1v.w = splith(a3.x, a3.y, l1v.w);
            h2v.x = splith(c0.x, c0.y, l2v.x); h2v.y = splith(c1.x, c1.y, l2v.y);
            h2v.z = splith(c2.x, c2.y, l2v.z); h2v.w = splith(c3.x, c3.y, l2v.w);
            char* sb = As + (slot ^ 1) * ASLOT + gc_ * 528;
            char* b1p = sb + (grg * 4 + gtig) * 16;
            char* b2p = sb + ((grg + 4) * 4 + gtig) * 16;
            *(uint4*)b1p = h1v; *(uint4*)(b1p + ALO) = l1v;
            *(uint4*)b2p = h2v; *(uint4*)(b2p + ALO) = l2v;
        }
        cp_wait<0>();
        __syncthreads();

        // ---- mid epilogue after layers 1 and 2: bias+ELU+split -> Af (STS.128) ----
        if (gcc == 11 || gcc == 15) {
            const float* bp = bias + ((gcc == 11) ? 0 : 256);
            #pragma unroll
            for (int i = 0; i < 4; ++i) {
                #pragma unroll
                for (int jp = 0; jp < 2; ++jp) {
                    uint4 hv, lv;
                    #pragma unroll
                    for (int u = 0; u < 2; ++u) {
                        int j = 2 * jp + u;
                        int cb = wn * 32 + j * 8 + tig * 2;
                        float b0v = bp[cb], b1v = bp[cb + 1];
                        float v0 = acc[i][j][0] + b0v, v1 = acc[i][j][1] + b1v;
                        float v2 = acc[i][j][2] + b0v, v3 = acc[i][j][3] + b1v;
                        v0 = v0 > 0.f ? v0 : (__expf(v0) - 1.f);
                        v1 = v1 > 0.f ? v1 : (__expf(v1) - 1.f);
                        v2 = v2 > 0.f ? v2 : (__expf(v2) - 1.f);
                        v3 = v3 > 0.f ? v3 : (__expf(v3) - 1.f);
                        if (u == 0) { hv.x = splith(v0, v1, lv.x); hv.y = splith(v2, v3, lv.y); }
                        else        { hv.z = splith(v0, v1, lv.z); hv.w = splith(v2, v3, lv.w); }
                        acc[i][j][0] = acc[i][j][1] = acc[i][j][2] = acc[i][j][3] = 0.f;
                    }
                    char* p = Af + ((i * 16 + wn * 2 + jp) * 32 + lane) * 16;
                    *(uint4*)p = hv;
                    *(uint4*)(p + AFLO) = lv;
                }
            }
            __syncthreads();
        }
    }

    // ---- final epilogue: acc + b2 + residual root embedding, direct stores ----
    #pragma unroll
    for (int i = 0; i < 4; ++i) {
        int r_g  = i * 16 + g;
        int r_g8 = r_g + 8;
        const float* e0p = rowptr[r_g];
        const float* e1p = rowptr[r_g8];
        #pragma unroll
        for (int j = 0; j < 4; ++j) {
            int cb = wn * 32 + j * 8 + tig * 2;
            float b0v = bias[512 + cb], b1v = bias[512 + cb + 1];
            float2 e0 = *(const float2*)(e0p + cb);
            float2 e1 = *(const float2*)(e1p + cb);
            float2 o0 = make_float2(acc[i][j][0] + b0v + e0.x, acc[i][j][1] + b1v + e0.y);
            float2 o1 = make_float2(acc[i][j][2] + b0v + e1.x, acc[i][j][3] + b1v + e1.y);
            if (level == 1) {
                *(float2*)(d_out + (size_t)r_g  * D + cb) = o0;
                *(float2*)(d_out + (size_t)r_g8 * D + cb) = o1;
            } else {
                *(float2*)(g_node_val + ((size_t)node * BATCH + r_g)  * D + cb) = o0;
                *(float2*)(g_node_val + ((size_t)node * BATCH + r_g8) * D + cb) = o1;
            }
        }
    }
}

extern "C" void kernel_launch(void* const* d_in, const int* in_sizes, int n_in,
                              void* d_out, int out_size) {
    const int*   tokens = (const int*)d_in[0];
    const float* E      = (const float*)d_in[1];
    const float* W_in   = (const float*)d_in[2];
    const float* b_in   = (const float*)d_in[3];
    const float* W1     = (const float*)d_in[4];
    const float* b1     = (const float*)d_in[5];
    const float* W2     = (const float*)d_in[6];
    const float* b2     = (const float*)d_in[7];
    float* out = (float*)d_out;

    cudaFuncSetAttribute(level_kernel, cudaFuncAttributeMaxDynamicSharedMemorySize, SMEM_TOTAL);

    prep_weights<<<(NCH * 4096) / 256, 256>>>(W_in, W1, W2);

    for (int level = 1024; level >= 1; level >>= 1) {
        level_kernel<<<level, 256, SMEM_TOTAL>>>(tokens, E, b_in, b1, b2, out, level);
    }
}

// round 9
// speedup vs baseline: 1.2745x; 1.1125x over previous
#include <cuda_runtime.h>
#include <cuda_bf16.h>
#include <cstdint>

#define BATCH 64
#define D 256
#define NTOK 4095
#define NCH 20             // 12 (layer1 K=768) + 4 (layer2) + 4 (layer3), K-chunk = 64

__device__ float g_node_val[2047 * BATCH * D];
__device__ __align__(256) uint4 g_W[NCH * 4096];   // 1.25 MB, fragment-major

// ---------------- SMEM layout (per block, ~70KB -> 2 blocks/SM) ----------------
#define ASLOT   16896      // layer-1 A slot: hi 16*528 + lo 16*528 (aliases Af region)
#define ALO     8448
#define AFLO    32768      // Af lo offset (hi: 4 tiles * 16 sg * 32 lanes * 16B = 32KB)
#define BIASOFF 65536
#define RPTROFF 68608
#define SMEM_TOTAL 70144

// ---------------- helpers ----------------
__device__ __forceinline__ void mma16816(float d[4], uint32_t a0, uint32_t a1, uint32_t a2, uint32_t a3,
                                         uint32_t b0, uint32_t b1) {
    asm volatile("mma.sync.aligned.m16n8k16.row.col.f32.bf16.bf16.f32 "
                 "{%0,%1,%2,%3}, {%4,%5,%6,%7}, {%8,%9}, {%0,%1,%2,%3};"
                 : "+f"(d[0]), "+f"(d[1]), "+f"(d[2]), "+f"(d[3])
                 : "r"(a0), "r"(a1), "r"(a2), "r"(a3), "r"(b0), "r"(b1));
}
__device__ __forceinline__ uint32_t b2u(__nv_bfloat162 v) { return *reinterpret_cast<uint32_t*>(&v); }
__device__ __forceinline__ uint32_t splith(float x, float y, uint32_t& l) {
    __nv_bfloat162 hh = __floats2bfloat162_rn(x, y);
    __nv_bfloat162 ll = __floats2bfloat162_rn(x - __bfloat162float(hh.x),
                                              y - __bfloat162float(hh.y));
    l = b2u(ll);
    return b2u(hh);
}

// -------- weight prep: fp32 -> hi/lo bf16, frag-major K64 chunks --------
// g_W[((gc*4+s)*32 + jt)*32 + lane] = {b0h, b1h, b0l, b1l}
__global__ void prep_weights(const float* __restrict__ W_in,
                             const float* __restrict__ W1,
                             const float* __restrict__ W2) {
    int idx = blockIdx.x * 256 + threadIdx.x;
    if (idx >= NCH * 4096) return;
    int lane = idx & 31;
    int jt   = (idx >> 5) & 31;
    int s    = (idx >> 10) & 3;
    int gcw  = idx >> 12;
    int n  = jt * 8 + (lane >> 2);
    int tg = lane & 3;
    const float* Wsrc; int K, kb;
    if (gcw < 12)      { Wsrc = W_in; K = 768; kb = gcw * 64; }
    else if (gcw < 16) { Wsrc = W1;   K = 256; kb = (gcw - 12) * 64; }
    else               { Wsrc = W2;   K = 256; kb = (gcw - 16) * 64; }
    int k0 = kb + s * 16 + tg * 2;
    uint32_t l0, l1;
    uint32_t h0 = splith(Wsrc[n * K + k0],     Wsrc[n * K + k0 + 1], l0);
    uint32_t h1 = splith(Wsrc[n * K + k0 + 8], Wsrc[n * K + k0 + 9], l1);
    g_W[idx] = make_uint4(h0, h1, l0, l1);
}

// B fragment LDG: 4 j-tiles for (chunk, kstep), warp-private slice, L2-resident
__device__ __forceinline__ void ldgB(uint4 B[4], int gc, int ks, int wn, int lane) {
    const uint4* wp = g_W + (((gc * 4 + ks) * 32) + wn * 4) * 32 + lane;
    B[0] = wp[0];
    B[1] = wp[32];
    B[2] = wp[64];
    B[3] = wp[96];
}

// ---------------- fused 3-layer MLP, M=64 node-block, 256 threads, 2 blocks/SM ----------------
__global__ void __launch_bounds__(256, 2)
level_kernel(const int* __restrict__ tokens, const float* __restrict__ E,
             const float* __restrict__ b_in, const float* __restrict__ b1,
             const float* __restrict__ b2, float* __restrict__ d_out, int level)
{
    extern __shared__ char smem[];
    float* bias = (float*)(smem + BIASOFF);
    const float** rowptr = (const float**)(smem + RPTROFF);
    char* As = smem;     // layer-1 A ring (2 x ASLOT), aliases Af
    char* Af = smem;     // resident activations for layers 2-3

    const int tid  = threadIdx.x;
    const int wn   = tid >> 5;        // warp: 32 output cols
    const int lane = tid & 31;
    const int g    = lane >> 2;
    const int tig  = lane & 3;
    const int node = level - 1 + blockIdx.x;

    // gather decode: combo c = t*4+s (t = m16 tile, s = kstep), 16 threads per combo
    const int gc_  = tid >> 4;
    const int grg  = (tid >> 2) & 3;
    const int gtig = tid & 3;
    const int gr0  = (gc_ >> 2) * 16 + grg;
    const int gs   = gc_ & 3;

    bias[tid]       = b_in[tid];
    bias[256 + tid] = b1[tid];
    bias[512 + tid] = b2[tid];
    if (tid < 64) {
        int b = tid;
        rowptr[tid] = E + (size_t)tokens[b * NTOK + node] * D;
        if (level == 1024) {
            rowptr[64 + tid]  = E + (size_t)tokens[b * NTOK + 2 * node + 1] * D;
            rowptr[128 + tid] = E + (size_t)tokens[b * NTOK + 2 * node + 2] * D;
        } else {
            rowptr[64 + tid]  = g_node_val + ((size_t)(2 * node + 1) * BATCH + b) * D;
            rowptr[128 + tid] = g_node_val + ((size_t)(2 * node + 2) * BATCH + b) * D;
        }
    }

    float acc[4][4][4];
    #pragma unroll
    for (int i = 0; i < 4; ++i)
        #pragma unroll
        for (int j = 0; j < 4; ++j)
            #pragma unroll
            for (int q = 0; q < 4; ++q) acc[i][j][q] = 0.f;

    __syncthreads();   // rowptr visible

    // ---- A(0) gather: conflict-tuned STS.128 fragment lines ----
    {
        const float* pr0 = rowptr[gr0];
        const float* pr1 = rowptr[gr0 + 8];
        const float* pr2 = rowptr[gr0 + 4];
        const float* pr3 = rowptr[gr0 + 12];
        int kb = gs * 16 + gtig * 2;
        float2 a0 = *(const float2*)(pr0 + kb),     a1 = *(const float2*)(pr1 + kb);
        float2 a2 = *(const float2*)(pr0 + kb + 8), a3 = *(const float2*)(pr1 + kb + 8);
        float2 c0 = *(const float2*)(pr2 + kb),     c1 = *(const float2*)(pr3 + kb);
        float2 c2 = *(const float2*)(pr2 + kb + 8), c3 = *(const float2*)(pr3 + kb + 8);
        uint4 h1v, l1v, h2v, l2v;
        h1v.x = splith(a0.x, a0.y, l1v.x); h1v.y = splith(a1.x, a1.y, l1v.y);
        h1v.z = splith(a2.x, a2.y, l1v.z); h1v.w = splith(a3.x, a3.y, l1v.w);
        h2v.x = splith(c0.x, c0.y, l2v.x); h2v.y = splith(c1.x, c1.y, l2v.y);
        h2v.z = splith(c2.x, c2.y, l2v.z); h2v.w = splith(c3.x, c3.y, l2v.w);
        char* b1p = As + gc_ * 528 + (grg * 4 + gtig) * 16;
        char* b2p = As + gc_ * 528 + ((grg + 4) * 4 + gtig) * 16;
        *(uint4*)b1p = h1v; *(uint4*)(b1p + ALO) = l1v;
        *(uint4*)b2p = h2v; *(uint4*)(b2p + ALO) = l2v;
    }
    __syncthreads();

    // ================= layer 1: chunks 0..11 (A ring, per-chunk barrier) =================
    for (int gcc = 0; gcc < 12; ++gcc) {
        const int slot = gcc & 1;
        const bool doGather = (gcc + 1 < 12);

        // prefetch next-chunk A rows (registers; latency hidden under MMAs)
        float2 a0, a1, a2, a3, c0, c1, c2, c3;
        if (doGather) {
            int gn = gcc + 1;
            int seg = gn >> 2;
            int kb = (gn & 3) * 64 + gs * 16 + gtig * 2;
            const float* pr0 = rowptr[seg * 64 + gr0];
            const float* pr1 = rowptr[seg * 64 + gr0 + 8];
            const float* pr2 = rowptr[seg * 64 + gr0 + 4];
            const float* pr3 = rowptr[seg * 64 + gr0 + 12];
            a0 = *(const float2*)(pr0 + kb);     a1 = *(const float2*)(pr1 + kb);
            a2 = *(const float2*)(pr0 + kb + 8); a3 = *(const float2*)(pr1 + kb + 8);
            c0 = *(const float2*)(pr2 + kb);     c1 = *(const float2*)(pr3 + kb);
            c2 = *(const float2*)(pr2 + kb + 8); c3 = *(const float2*)(pr3 + kb + 8);
        }

        // compute: K=64, B via LDG with one-kstep prefetch
        const char* ab = As + slot * ASLOT;
        uint4 B[4];
        ldgB(B, gcc, 0, wn, lane);
        #pragma unroll
        for (int ks = 0; ks < 4; ++ks) {
            uint4 Bn[4];
            if (ks < 3) ldgB(Bn, gcc, ks + 1, wn, lane);
            #pragma unroll
            for (int half = 0; half < 2; ++half) {
                uint4 Ahi[2], Alo[2];
                #pragma unroll
                for (int i2 = 0; i2 < 2; ++i2) {
                    const char* p = ab + ((half * 2 + i2) * 4 + ks) * 528 + lane * 16;
                    Ahi[i2] = *(const uint4*)p;
                    Alo[i2] = *(const uint4*)(p + ALO);
                }
                #pragma unroll
                for (int j = 0; j < 4; ++j)
                    #pragma unroll
                    for (int i2 = 0; i2 < 2; ++i2) {
                        float* a = acc[half * 2 + i2][j];
                        mma16816(a, Ahi[i2].x, Ahi[i2].y, Ahi[i2].z, Ahi[i2].w, B[j].x, B[j].y);
                        mma16816(a, Ahi[i2].x, Ahi[i2].y, Ahi[i2].z, Ahi[i2].w, B[j].z, B[j].w);
                        mma16816(a, Alo[i2].x, Alo[i2].y, Alo[i2].z, Alo[i2].w, B[j].x, B[j].y);
                    }
            }
            if (ks < 3) { B[0] = Bn[0]; B[1] = Bn[1]; B[2] = Bn[2]; B[3] = Bn[3]; }
        }

        // store prefetched A into other slot
        if (doGather) {
            uint4 h1v, l1v, h2v, l2v;
            h1v.x = splith(a0.x, a0.y, l1v.x); h1v.y = splith(a1.x, a1.y, l1v.y);
            h1v.z = splith(a2.x, a2.y, l1v.z); h1v.w = splith(a3.x, a3.y, l1v.w);
            h2v.x = splith(c0.x, c0.y, l2v.x); h2v.y = splith(c1.x, c1.y, l2v.y);
            h2v.z = splith(c2.x, c2.y, l2v.z); h2v.w = splith(c3.x, c3.y, l2v.w);
            char* sb = As + (slot ^ 1) * ASLOT + gc_ * 528;
            char* b1p = sb + (grg * 4 + gtig) * 16;
            char* b2p = sb + ((grg + 4) * 4 + gtig) * 16;
            *(uint4*)b1p = h1v; *(uint4*)(b1p + ALO) = l1v;
            *(uint4*)b2p = h2v; *(uint4*)(b2p + ALO) = l2v;
        }
        __syncthreads();
    }

    // ---- mid epilogue 1: bias+ELU+split -> Af (overwrites A ring; all reads done) ----
    #pragma unroll
    for (int i = 0; i < 4; ++i) {
        #pragma unroll
        for (int jp = 0; jp < 2; ++jp) {
            uint4 hv, lv;
            #pragma unroll
            for (int u = 0; u < 2; ++u) {
                int j = 2 * jp + u;
                int cb = wn * 32 + j * 8 + tig * 2;
                float b0v = bias[cb], b1v = bias[cb + 1];
                float v0 = acc[i][j][0] + b0v, v1 = acc[i][j][1] + b1v;
                float v2 = acc[i][j][2] + b0v, v3 = acc[i][j][3] + b1v;
                v0 = v0 > 0.f ? v0 : (__expf(v0) - 1.f);
                v1 = v1 > 0.f ? v1 : (__expf(v1) - 1.f);
                v2 = v2 > 0.f ? v2 : (__expf(v2) - 1.f);
                v3 = v3 > 0.f ? v3 : (__expf(v3) - 1.f);
                if (u == 0) { hv.x = splith(v0, v1, lv.x); hv.y = splith(v2, v3, lv.y); }
                else        { hv.z = splith(v0, v1, lv.z); hv.w = splith(v2, v3, lv.w); }
                acc[i][j][0] = acc[i][j][1] = acc[i][j][2] = acc[i][j][3] = 0.f;
            }
            char* p = Af + ((i * 16 + wn * 2 + jp) * 32 + lane) * 16;
            *(uint4*)p = hv;
            *(uint4*)(p + AFLO) = lv;
        }
    }
    __syncthreads();

    // ================= layers 2 & 3: barrier-free chunks from resident Af =================
    #pragma unroll 1
    for (int layer = 1; layer <= 2; ++layer) {
        const int gbase = (layer == 1) ? 12 : 16;
        #pragma unroll 1
        for (int c = 0; c < 4; ++c) {
            const int gcw = gbase + c;
            uint4 B[4];
            ldgB(B, gcw, 0, wn, lane);
            #pragma unroll
            for (int ks = 0; ks < 4; ++ks) {
                uint4 Bn[4];
                if (ks < 3) ldgB(Bn, gcw, ks + 1, wn, lane);
                int sg = c * 4 + ks;
                #pragma unroll
                for (int half = 0; half < 2; ++half) {
                    uint4 Ahi[2], Alo[2];
                    #pragma unroll
                    for (int i2 = 0; i2 < 2; ++i2) {
                        const char* p = Af + (((half * 2 + i2) * 16 + sg) * 32 + lane) * 16;
                        Ahi[i2] = *(const uint4*)p;
                        Alo[i2] = *(const uint4*)(p + AFLO);
                    }
                    #pragma unroll
                    for (int j = 0; j < 4; ++j)
                        #pragma unroll
                        for (int i2 = 0; i2 < 2; ++i2) {
                            float* a = acc[half * 2 + i2][j];
                            mma16816(a, Ahi[i2].x, Ahi[i2].y, Ahi[i2].z, Ahi[i2].w, B[j].x, B[j].y);
                            mma16816(a, Ahi[i2].x, Ahi[i2].y, Ahi[i2].z, Ahi[i2].w, B[j].z, B[j].w);
                            mma16816(a, Alo[i2].x, Alo[i2].y, Alo[i2].z, Alo[i2].w, B[j].x, B[j].y);
                        }
                }
                if (ks < 3) { B[0] = Bn[0]; B[1] = Bn[1]; B[2] = Bn[2]; B[3] = Bn[3]; }
            }
        }

        if (layer == 1) {
            // mid epilogue 2: all warps must finish reading layer-1 Af before overwrite
            __syncthreads();
            #pragma unroll
            for (int i = 0; i < 4; ++i) {
                #pragma unroll
                for (int jp = 0; jp < 2; ++jp) {
                    uint4 hv, lv;
                    #pragma unroll
                    for (int u = 0; u < 2; ++u) {
                        int j = 2 * jp + u;
                        int cb = wn * 32 + j * 8 + tig * 2;
                        float b0v = bias[256 + cb], b1v = bias[256 + cb + 1];
                        float v0 = acc[i][j][0] + b0v, v1 = acc[i][j][1] + b1v;
                        float v2 = acc[i][j][2] + b0v, v3 = acc[i][j][3] + b1v;
                        v0 = v0 > 0.f ? v0 : (__expf(v0) - 1.f);
                        v1 = v1 > 0.f ? v1 : (__expf(v1) - 1.f);
                        v2 = v2 > 0.f ? v2 : (__expf(v2) - 1.f);
                        v3 = v3 > 0.f ? v3 : (__expf(v3) - 1.f);
                        if (u == 0) { hv.x = splith(v0, v1, lv.x); hv.y = splith(v2, v3, lv.y); }
                        else        { hv.z = splith(v0, v1, lv.z); hv.w = splith(v2, v3, lv.w); }
                        acc[i][j][0] = acc[i][j][1] = acc[i][j][2] = acc[i][j][3] = 0.f;
                    }
                    char* p = Af + ((i * 16 + wn * 2 + jp) * 32 + lane) * 16;
                    *(uint4*)p = hv;
                    *(uint4*)(p + AFLO) = lv;
                }
            }
            __syncthreads();
        }
    }

    // ---- final epilogue: acc + b2 + residual root embedding, direct stores ----
    #pragma unroll
    for (int i = 0; i < 4; ++i) {
        int r_g  = i * 16 + g;
        int r_g8 = r_g + 8;
        const float* e0p = rowptr[r_g];
        const float* e1p = rowptr[r_g8];
        #pragma unroll
        for (int j = 0; j < 4; ++j) {
            int cb = wn * 32 + j * 8 + tig * 2;
            float b0v = bias[512 + cb], b1v = bias[512 + cb + 1];
            float2 e0 = *(const float2*)(e0p + cb);
            float2 e1 = *(const float2*)(e1p + cb);
            float2 o0 = make_float2(acc[i][j][0] + b0v + e0.x, acc[i][j][1] + b1v + e0.y);
            float2 o1 = make_float2(acc[i][j][2] + b0v + e1.x, acc[i][j][3] + b1v + e1.y);
            if (level == 1) {
                *(float2*)(d_out + (size_t)r_g  * D + cb) = o0;
                *(float2*)(d_out + (size_t)r_g8 * D + cb) = o1;
            } else {
                *(float2*)(g_node_val + ((size_t)node * BATCH + r_g)  * D + cb) = o0;
                *(float2*)(g_node_val + ((size_t)node * BATCH + r_g8) * D + cb) = o1;
            }
        }
    }
}

extern "C" void kernel_launch(void* const* d_in, const int* in_sizes, int n_in,
                              void* d_out, int out_size) {
    const int*   tokens = (const int*)d_in[0];
    const float* E      = (const float*)d_in[1];
    const float* W_in   = (const float*)d_in[2];
    const float* b_in   = (const float*)d_in[3];
    const float* W1     = (const float*)d_in[4];
    const float* b1     = (const float*)d_in[5];
    const float* W2     = (const float*)d_in[6];
    const float* b2     = (const float*)d_in[7];
    float* out = (float*)d_out;

    cudaFuncSetAttribute(level_kernel, cudaFuncAttributeMaxDynamicSharedMemorySize, SMEM_TOTAL);

    prep_weights<<<(NCH * 4096) / 256, 256>>>(W_in, W1, W2);

    for (int level = 1024; level >= 1; level >>= 1) {
        level_kernel<<<level, 256, SMEM_TOTAL>>>(tokens, E, b_in, b1, b2, out, level);
    }
}